// round 10
// baseline (speedup 1.0000x reference)
#include <cuda_runtime.h>
#include <math_constants.h>
#include <cstdint>

// Shapes (fixed):
//   word_features  [B, D, T]   = [32, 256, 32]   fp32   d_in[0]
//   image_features [B, Dh,H,W] = [32, 128,128,128] fp32 d_in[1]
//   words_mask     [B, T]      = [32, 32]        int32  d_in[2]
//   W              [Dh, D]     = [128, 256]      fp32   d_in[3]
//   b              [Dh]        = [128]           fp32   d_in[4]
// Outputs: attn [B,Dh,N] at 0, attn_coefficients [B,N,T] at B*Dh*N.
//
// Masked t columns contribute exactly zero; t is compacted per batch (padded
// to a multiple of 8, JM = Tcp/8). Four JM-specialized kernels are launched;
// each CTA computes its batch's compaction in-CTA (warp ballot) and early-
// exits unless jm matches, so each width gets its own register allocation
// (JM1/JM2 run 3 CTAs/SM).

#define B_   32
#define D_   256
#define T_   32
#define DH_  128
#define N_   16384

__device__ float g_values[B_ * DH_ * T_];

// ---------------- packed f32x2 helpers ----------------
__device__ __forceinline__ unsigned long long pk2(float lo, float hi) {
    unsigned long long r;
    asm("mov.b64 %0, {%1, %2};" : "=l"(r) : "f"(lo), "f"(hi));
    return r;
}
__device__ __forceinline__ float2 unpk2(unsigned long long v) {
    float2 f;
    asm("mov.b64 {%0, %1}, %2;" : "=f"(f.x), "=f"(f.y) : "l"(v));
    return f;
}
__device__ __forceinline__ unsigned long long ffma2(unsigned long long a,
                                                    unsigned long long b,
                                                    unsigned long long c) {
    unsigned long long d;
    asm("fma.rn.f32x2 %0, %1, %2, %3;" : "=l"(d) : "l"(a), "l"(b), "l"(c));
    return d;
}
__device__ __forceinline__ unsigned long long add2(unsigned long long a,
                                                   unsigned long long b) {
    unsigned long long d;
    asm("add.rn.f32x2 %0, %1, %2;" : "=l"(d) : "l"(a), "l"(b));
    return d;
}

// ---------------- kernel 1: values = W * wf + b ----------------
#define SW_PAD 264
__global__ __launch_bounds__(256)
void values_kernel(const float* __restrict__ wf,
                   const float* __restrict__ Wm,
                   const float* __restrict__ bias) {
    __shared__ float swf[D_ * T_];
    __shared__ float sW[32 * SW_PAD];
    const int c = blockIdx.x;
    const int b = blockIdx.y;
    const int tid = threadIdx.x;

    {
        const float4* src =
            reinterpret_cast<const float4*>(wf + (size_t)b * D_ * T_);
        float4* dst = reinterpret_cast<float4*>(swf);
#pragma unroll
        for (int i = 0; i < 8; i++) dst[tid + 256 * i] = src[tid + 256 * i];

        const float4* wsrc =
            reinterpret_cast<const float4*>(Wm + (size_t)c * 32 * D_);
#pragma unroll
        for (int i = 0; i < 8; i++) {
            const int idx = tid + 256 * i;
            const int kl = idx >> 6;
            const int dc = idx & 63;
            float4 v = wsrc[idx];
            *reinterpret_cast<float4*>(&sW[kl * SW_PAD + dc * 4]) = v;
        }
    }
    __syncthreads();

    const int k_l = tid >> 3;
    const int tq = tid & 7;
    const int k = c * 32 + k_l;

    const float bk = bias[k];
    unsigned long long acc0 = pk2(bk, bk);
    unsigned long long acc1 = pk2(bk, bk);

#pragma unroll 4
    for (int d = 0; d < D_; d++) {
        const float w = sW[k_l * SW_PAD + d];
        const unsigned long long wp = pk2(w, w);
        const ulonglong2 v =
            *reinterpret_cast<const ulonglong2*>(&swf[d * T_ + tq * 4]);
        acc0 = ffma2(wp, v.x, acc0);
        acc1 = ffma2(wp, v.y, acc1);
    }

    ulonglong2 o;
    o.x = acc0;
    o.y = acc1;
    *reinterpret_cast<ulonglong2*>(
        g_values + ((size_t)b * DH_ + k) * T_ + tq * 4) = o;
}

// ---------------- JM-specialized attention kernel ----------------
// block = 256 (8 warps), grid = (N/512, B). Lane pair (2p,2p+1) shares 4
// pixels; even lane owns compact cols [0,4JM), odd [4JM,8JM). Each CTA
// computes the per-batch compaction via ballot and exits unless jm == JM.
template <int JM, int MINB>
__global__ __launch_bounds__(256, MINB)
void attn_kernel_t(const float* __restrict__ img,
                   const int* __restrict__ mask,
                   float* __restrict__ out_attn,
                   float* __restrict__ out_coef) {
    __shared__ __align__(16) float svf[DH_ * T_];
    __shared__ __align__(8) float scs[T_];
    __shared__ int stl[T_];
    __shared__ int sjm;

    const int b = blockIdx.y;
    const int tid = threadIdx.x;
    const int lane = tid & 31;
    const int warp = tid >> 5;
    const int half = lane & 1;
    const int pair = lane >> 1;
    const int n0 = blockIdx.x * 512 + warp * 64 + pair * 4;

    // in-CTA mask compaction (warp 0)
    if (tid < 32) {
        const int m = mask[b * T_ + tid];
        const unsigned bal = __ballot_sync(0xffffffffu, m == 0);
        const int Tc = __popc(bal);
        int Tcp = (Tc + 7) & ~7;
        if (Tcp < 8) Tcp = 8;
        if (m == 0) {
            const int pos = __popc(bal & ((1u << tid) - 1u));
            stl[pos] = tid;
        }
        const unsigned mb = ~bal;
        const int firstMasked = mb ? (__ffs(mb) - 1) : 0;
        if (tid >= Tc) stl[tid] = firstMasked;
        scs[tid] = (tid < Tc) ? 0.0f : -CUDART_INF_F;
        if (tid == 0) sjm = Tcp >> 3;
    }
    __syncthreads();
    if (sjm != JM) return;

    // gather compact values rows (permutation within 128B lines)
    {
        const float* gvb = g_values + (size_t)b * DH_ * T_;
#pragma unroll
        for (int i = 0; i < 16; i++) {
            const int f = tid + 256 * i;
            svf[f] = gvb[(f & ~31) + stl[f & 31]];
        }
    }
    __syncthreads();

    constexpr int NJ = 2 * JM;
    const int cb = half * 4 * JM;
    const ulonglong2* svals = reinterpret_cast<const ulonglong2*>(svf);

    unsigned long long acc[4][NJ];
#pragma unroll
    for (int px = 0; px < 4; px++)
#pragma unroll
        for (int j = 0; j < NJ; j++) acc[px][j] = 0ULL;

    // ---- phase 1: S_compact = sum_k q * vals_compact ----
    const float4* qb =
        reinterpret_cast<const float4*>(img + (size_t)b * DH_ * N_ + n0);
    float4 qv[4];
#pragma unroll
    for (int kk = 0; kk < 4; kk++) qv[kk] = qb[(size_t)kk * (N_ / 4)];

    for (int k = 0; k < DH_; k += 4) {
        float4 qn[4];
        if (k + 4 < DH_) {
#pragma unroll
            for (int kk = 0; kk < 4; kk++)
                qn[kk] = qb[(size_t)(k + 4 + kk) * (N_ / 4)];
        }
#pragma unroll
        for (int kk = 0; kk < 4; kk++) {
            const unsigned long long q0 = pk2(qv[kk].x, qv[kk].x);
            const unsigned long long q1 = pk2(qv[kk].y, qv[kk].y);
            const unsigned long long q2 = pk2(qv[kk].z, qv[kk].z);
            const unsigned long long q3 = pk2(qv[kk].w, qv[kk].w);
            const ulonglong2* vr = &svals[(size_t)(k + kk) * 8 + half * JM];
#pragma unroll
            for (int j = 0; j < JM; j++) {
                const ulonglong2 v = vr[j];
                acc[0][2 * j + 0] = ffma2(q0, v.x, acc[0][2 * j + 0]);
                acc[0][2 * j + 1] = ffma2(q0, v.y, acc[0][2 * j + 1]);
                acc[1][2 * j + 0] = ffma2(q1, v.x, acc[1][2 * j + 0]);
                acc[1][2 * j + 1] = ffma2(q1, v.y, acc[1][2 * j + 1]);
                acc[2][2 * j + 0] = ffma2(q2, v.x, acc[2][2 * j + 0]);
                acc[2][2 * j + 1] = ffma2(q2, v.y, acc[2][2 * j + 1]);
                acc[3][2 * j + 0] = ffma2(q3, v.x, acc[3][2 * j + 0]);
                acc[3][2 * j + 1] = ffma2(q3, v.y, acc[3][2 * j + 1]);
            }
        }
#pragma unroll
        for (int kk = 0; kk < 4; kk++) qv[kk] = qn[kk];
    }

    // ---- zero-fill coefficient rows (pair covers full 32-col row) ----
    float* ocb = out_coef + ((size_t)b * N_ + n0) * T_;
#pragma unroll
    for (int px = 0; px < 4; px++) {
        float4* z = reinterpret_cast<float4*>(ocb + px * T_ + half * 16);
#pragma unroll
        for (int j = 0; j < 4; j++) z[j] = make_float4(0.f, 0.f, 0.f, 0.f);
    }

    // ---- phase 2: softmax over compact cols (pads -> -inf -> 0) ----
    unsigned long long sn[NJ];
    {
        const unsigned long long* snp =
            reinterpret_cast<const unsigned long long*>(&scs[cb]);
#pragma unroll
        for (int j = 0; j < NJ; j++) sn[j] = snp[j];
    }
#pragma unroll
    for (int px = 0; px < 4; px++) {
        float Sv[2 * NJ];
#pragma unroll
        for (int j = 0; j < NJ; j++) {
            const float2 f = unpk2(add2(acc[px][j], sn[j]));
            Sv[2 * j + 0] = f.x;
            Sv[2 * j + 1] = f.y;
        }
        float m = -CUDART_INF_F;
#pragma unroll
        for (int i = 0; i < 2 * NJ; i++) m = fmaxf(m, Sv[i]);
        m = fmaxf(m, __shfl_xor_sync(0xffffffffu, m, 1));
        float sum = 0.f;
#pragma unroll
        for (int i = 0; i < 2 * NJ; i++) {
            Sv[i] = __expf(Sv[i] - m);
            sum += Sv[i];
        }
        sum += __shfl_xor_sync(0xffffffffu, sum, 1);
        const float inv = 1.0f / sum;
#pragma unroll
        for (int i = 0; i < 2 * NJ; i++) Sv[i] *= inv;
#pragma unroll
        for (int j = 0; j < NJ; j++)
            acc[px][j] = pk2(Sv[2 * j], Sv[2 * j + 1]);
    }

    // ---- scatter coefficients (pads write exact 0 to a masked col) ----
    __syncwarp();  // order partner's zero-fill before scatter
#pragma unroll
    for (int px = 0; px < 4; px++) {
        float* oc = ocb + px * T_;
#pragma unroll
        for (int j = 0; j < NJ; j++) {
            const float2 f = unpk2(acc[px][j]);
            oc[stl[cb + 2 * j + 0]] = f.x;
            oc[stl[cb + 2 * j + 1]] = f.y;
        }
    }

    // ---- phase 3: attn[k] = sum_compact vals * p, half-t partials ----
    float* oa = out_attn + (size_t)b * DH_ * N_ + n0 + 2 * half;
    for (int k = 0; k < DH_; k += 4) {
        unsigned long long mine[4], sent[4];
#pragma unroll
        for (int kk = 0; kk < 4; kk++) {
            const ulonglong2* vr = &svals[(size_t)(k + kk) * 8 + half * JM];
            unsigned long long a0 = 0ULL, a1 = 0ULL, a2 = 0ULL, a3 = 0ULL;
#pragma unroll
            for (int j = 0; j < JM; j++) {
                const ulonglong2 v = vr[j];
                a0 = ffma2(v.x, acc[0][2 * j + 0], a0);
                a0 = ffma2(v.y, acc[0][2 * j + 1], a0);
                a1 = ffma2(v.x, acc[1][2 * j + 0], a1);
                a1 = ffma2(v.y, acc[1][2 * j + 1], a1);
                a2 = ffma2(v.x, acc[2][2 * j + 0], a2);
                a2 = ffma2(v.y, acc[2][2 * j + 1], a2);
                a3 = ffma2(v.x, acc[3][2 * j + 0], a3);
                a3 = ffma2(v.y, acc[3][2 * j + 1], a3);
            }
            const float2 f0 = unpk2(a0), f1 = unpk2(a1);
            const float2 f2 = unpk2(a2), f3 = unpk2(a3);
            const unsigned long long p01 = pk2(f0.x + f0.y, f1.x + f1.y);
            const unsigned long long p23 = pk2(f2.x + f2.y, f3.x + f3.y);
            sent[kk] = half ? p01 : p23;
            mine[kk] = half ? p23 : p01;
        }
        unsigned long long got[4];
#pragma unroll
        for (int kk = 0; kk < 4; kk++)
            got[kk] = __shfl_xor_sync(0xffffffffu, sent[kk], 1);
#pragma unroll
        for (int kk = 0; kk < 4; kk++) {
            const float2 r = unpk2(add2(mine[kk], got[kk]));
            *reinterpret_cast<float2*>(oa + (size_t)(k + kk) * N_) =
                make_float2(r.x, r.y);
        }
    }
}

extern "C" void kernel_launch(void* const* d_in, const int* in_sizes, int n_in,
                              void* d_out, int out_size) {
    const float* wf   = (const float*)d_in[0];
    const float* img  = (const float*)d_in[1];
    const int*   msk  = (const int*)d_in[2];
    const float* Wm   = (const float*)d_in[3];
    const float* bias = (const float*)d_in[4];

    float* out_attn = (float*)d_out;
    float* out_coef = (float*)d_out + (size_t)B_ * DH_ * N_;

    dim3 vgrid(4, B_);
    values_kernel<<<vgrid, 256>>>(wf, Wm, bias);

    dim3 grid(N_ / 512, B_);
    attn_kernel_t<2, 3><<<grid, 256>>>(img, msk, out_attn, out_coef);
    attn_kernel_t<3, 2><<<grid, 256>>>(img, msk, out_attn, out_coef);
    attn_kernel_t<1, 3><<<grid, 256>>>(img, msk, out_attn, out_coef);
    attn_kernel_t<4, 2><<<grid, 256>>>(img, msk, out_attn, out_coef);
}

// round 11
// speedup vs baseline: 1.1889x; 1.1889x over previous
#include <cuda_runtime.h>
#include <math_constants.h>
#include <cstdint>

// Shapes (fixed):
//   word_features  [B, D, T]   = [32, 256, 32]   fp32   d_in[0]
//   image_features [B, Dh,H,W] = [32, 128,128,128] fp32 d_in[1]
//   words_mask     [B, T]      = [32, 32]        int32  d_in[2]
//   W              [Dh, D]     = [128, 256]      fp32   d_in[3]
//   b              [Dh]        = [128]           fp32   d_in[4]
// Outputs: attn [B,Dh,N] at 0, attn_coefficients [B,N,T] at B*Dh*N.
//
// Masked t columns contribute exactly zero; t is compacted per batch (padded
// to a multiple of 8, JM = Tcp/8). Compaction is computed in-CTA (warp
// ballot); a single kernel dispatches to JM-templated cores at runtime so all
// batches run in one wave.

#define B_   32
#define D_   256
#define T_   32
#define DH_  128
#define N_   16384

__device__ float g_values[B_ * DH_ * T_];

// ---------------- packed f32x2 helpers ----------------
__device__ __forceinline__ unsigned long long pk2(float lo, float hi) {
    unsigned long long r;
    asm("mov.b64 %0, {%1, %2};" : "=l"(r) : "f"(lo), "f"(hi));
    return r;
}
__device__ __forceinline__ float2 unpk2(unsigned long long v) {
    float2 f;
    asm("mov.b64 {%0, %1}, %2;" : "=f"(f.x), "=f"(f.y) : "l"(v));
    return f;
}
__device__ __forceinline__ unsigned long long ffma2(unsigned long long a,
                                                    unsigned long long b,
                                                    unsigned long long c) {
    unsigned long long d;
    asm("fma.rn.f32x2 %0, %1, %2, %3;" : "=l"(d) : "l"(a), "l"(b), "l"(c));
    return d;
}
__device__ __forceinline__ unsigned long long add2(unsigned long long a,
                                                   unsigned long long b) {
    unsigned long long d;
    asm("add.rn.f32x2 %0, %1, %2;" : "=l"(d) : "l"(a), "l"(b));
    return d;
}

// ---------------- kernel 1: values = W * wf + b ----------------
#define SW_PAD 264
__global__ __launch_bounds__(256)
void values_kernel(const float* __restrict__ wf,
                   const float* __restrict__ Wm,
                   const float* __restrict__ bias) {
    __shared__ float swf[D_ * T_];
    __shared__ float sW[32 * SW_PAD];
    const int c = blockIdx.x;
    const int b = blockIdx.y;
    const int tid = threadIdx.x;

    {
        const float4* src =
            reinterpret_cast<const float4*>(wf + (size_t)b * D_ * T_);
        float4* dst = reinterpret_cast<float4*>(swf);
#pragma unroll
        for (int i = 0; i < 8; i++) dst[tid + 256 * i] = src[tid + 256 * i];

        const float4* wsrc =
            reinterpret_cast<const float4*>(Wm + (size_t)c * 32 * D_);
#pragma unroll
        for (int i = 0; i < 8; i++) {
            const int idx = tid + 256 * i;
            const int kl = idx >> 6;
            const int dc = idx & 63;
            float4 v = wsrc[idx];
            *reinterpret_cast<float4*>(&sW[kl * SW_PAD + dc * 4]) = v;
        }
    }
    __syncthreads();

    const int k_l = tid >> 3;
    const int tq = tid & 7;
    const int k = c * 32 + k_l;

    const float bk = bias[k];
    unsigned long long acc0 = pk2(bk, bk);
    unsigned long long acc1 = pk2(bk, bk);

#pragma unroll 4
    for (int d = 0; d < D_; d++) {
        const float w = sW[k_l * SW_PAD + d];
        const unsigned long long wp = pk2(w, w);
        const ulonglong2 v =
            *reinterpret_cast<const ulonglong2*>(&swf[d * T_ + tq * 4]);
        acc0 = ffma2(wp, v.x, acc0);
        acc1 = ffma2(wp, v.y, acc1);
    }

    ulonglong2 o;
    o.x = acc0;
    o.y = acc1;
    *reinterpret_cast<ulonglong2*>(
        g_values + ((size_t)b * DH_ + k) * T_ + tq * 4) = o;
}

// ---------------- templated attention core (JM = Tcp/8, 1..4) ----------------
// Lane pair (2p,2p+1) shares 4 pixels; even lane owns compact cols
// [0, 4*JM), odd lane [4*JM, 8*JM). Phase 3 combines halves via one 64-bit
// shuffle per k (batched by 4).
template <int JM>
__device__ __forceinline__ void attn_core(
    const ulonglong2* __restrict__ svals,  // [DH_][8] compact rows
    const float* __restrict__ scs,         // compact sneg
    const int* __restrict__ stl,           // compact -> original t
    const float4* __restrict__ qb,
    float* __restrict__ ocb,               // out_coef + (b*N+n0)*T_
    float* __restrict__ oa,                // out_attn + b*Dh*N + n0 + 2*half
    const int half) {
    constexpr int NJ = 2 * JM;       // packed accumulators per pixel
    const int cb = half * 4 * JM;    // compact float-col base for this lane

    unsigned long long acc[4][NJ];
#pragma unroll
    for (int px = 0; px < 4; px++)
#pragma unroll
        for (int j = 0; j < NJ; j++) acc[px][j] = 0ULL;

    // ---- phase 1: S_compact = sum_k q * vals_compact ----
    float4 qv[4];
#pragma unroll
    for (int kk = 0; kk < 4; kk++) qv[kk] = qb[(size_t)kk * (N_ / 4)];

    for (int k = 0; k < DH_; k += 4) {
        float4 qn[4];
        if (k + 4 < DH_) {
#pragma unroll
            for (int kk = 0; kk < 4; kk++)
                qn[kk] = qb[(size_t)(k + 4 + kk) * (N_ / 4)];
        }
#pragma unroll
        for (int kk = 0; kk < 4; kk++) {
            const unsigned long long q0 = pk2(qv[kk].x, qv[kk].x);
            const unsigned long long q1 = pk2(qv[kk].y, qv[kk].y);
            const unsigned long long q2 = pk2(qv[kk].z, qv[kk].z);
            const unsigned long long q3 = pk2(qv[kk].w, qv[kk].w);
            const ulonglong2* vr = &svals[(size_t)(k + kk) * 8 + half * JM];
#pragma unroll
            for (int j = 0; j < JM; j++) {
                const ulonglong2 v = vr[j];
                acc[0][2 * j + 0] = ffma2(q0, v.x, acc[0][2 * j + 0]);
                acc[0][2 * j + 1] = ffma2(q0, v.y, acc[0][2 * j + 1]);
                acc[1][2 * j + 0] = ffma2(q1, v.x, acc[1][2 * j + 0]);
                acc[1][2 * j + 1] = ffma2(q1, v.y, acc[1][2 * j + 1]);
                acc[2][2 * j + 0] = ffma2(q2, v.x, acc[2][2 * j + 0]);
                acc[2][2 * j + 1] = ffma2(q2, v.y, acc[2][2 * j + 1]);
                acc[3][2 * j + 0] = ffma2(q3, v.x, acc[3][2 * j + 0]);
                acc[3][2 * j + 1] = ffma2(q3, v.y, acc[3][2 * j + 1]);
            }
        }
#pragma unroll
        for (int kk = 0; kk < 4; kk++) qv[kk] = qn[kk];
    }

    // ---- zero-fill coefficient rows (pair covers full 32-col row) ----
#pragma unroll
    for (int px = 0; px < 4; px++) {
        float4* z = reinterpret_cast<float4*>(ocb + px * T_ + half * 16);
#pragma unroll
        for (int j = 0; j < 4; j++) z[j] = make_float4(0.f, 0.f, 0.f, 0.f);
    }

    // ---- phase 2: softmax over compact cols (pads -> -inf -> 0) ----
    unsigned long long sn[NJ];
    {
        const unsigned long long* snp =
            reinterpret_cast<const unsigned long long*>(&scs[cb]);
#pragma unroll
        for (int j = 0; j < NJ; j++) sn[j] = snp[j];
    }
#pragma unroll
    for (int px = 0; px < 4; px++) {
        float Sv[2 * NJ];
#pragma unroll
        for (int j = 0; j < NJ; j++) {
            const float2 f = unpk2(add2(acc[px][j], sn[j]));
            Sv[2 * j + 0] = f.x;
            Sv[2 * j + 1] = f.y;
        }
        float m = -CUDART_INF_F;
#pragma unroll
        for (int i = 0; i < 2 * NJ; i++) m = fmaxf(m, Sv[i]);
        m = fmaxf(m, __shfl_xor_sync(0xffffffffu, m, 1));
        float sum = 0.f;
#pragma unroll
        for (int i = 0; i < 2 * NJ; i++) {
            Sv[i] = __expf(Sv[i] - m);
            sum += Sv[i];
        }
        sum += __shfl_xor_sync(0xffffffffu, sum, 1);
        const float inv = 1.0f / sum;
#pragma unroll
        for (int i = 0; i < 2 * NJ; i++) Sv[i] *= inv;
#pragma unroll
        for (int j = 0; j < NJ; j++)
            acc[px][j] = pk2(Sv[2 * j], Sv[2 * j + 1]);
    }

    // ---- scatter coefficients (pads write exact 0 to a masked col) ----
    __syncwarp();  // order partner's zero-fill before scatter
#pragma unroll
    for (int px = 0; px < 4; px++) {
        float* oc = ocb + px * T_;
#pragma unroll
        for (int j = 0; j < NJ; j++) {
            const float2 f = unpk2(acc[px][j]);
            oc[stl[cb + 2 * j + 0]] = f.x;
            oc[stl[cb + 2 * j + 1]] = f.y;
        }
    }

    // ---- phase 3: attn[k] = sum_compact vals * p, half-t partials ----
    for (int k = 0; k < DH_; k += 4) {
        unsigned long long mine[4], sent[4];
#pragma unroll
        for (int kk = 0; kk < 4; kk++) {
            const ulonglong2* vr = &svals[(size_t)(k + kk) * 8 + half * JM];
            unsigned long long a0 = 0ULL, a1 = 0ULL, a2 = 0ULL, a3 = 0ULL;
#pragma unroll
            for (int j = 0; j < JM; j++) {
                const ulonglong2 v = vr[j];
                a0 = ffma2(v.x, acc[0][2 * j + 0], a0);
                a0 = ffma2(v.y, acc[0][2 * j + 1], a0);
                a1 = ffma2(v.x, acc[1][2 * j + 0], a1);
                a1 = ffma2(v.y, acc[1][2 * j + 1], a1);
                a2 = ffma2(v.x, acc[2][2 * j + 0], a2);
                a2 = ffma2(v.y, acc[2][2 * j + 1], a2);
                a3 = ffma2(v.x, acc[3][2 * j + 0], a3);
                a3 = ffma2(v.y, acc[3][2 * j + 1], a3);
            }
            const float2 f0 = unpk2(a0), f1 = unpk2(a1);
            const float2 f2 = unpk2(a2), f3 = unpk2(a3);
            const unsigned long long p01 = pk2(f0.x + f0.y, f1.x + f1.y);
            const unsigned long long p23 = pk2(f2.x + f2.y, f3.x + f3.y);
            sent[kk] = half ? p01 : p23;
            mine[kk] = half ? p23 : p01;
        }
        unsigned long long got[4];
#pragma unroll
        for (int kk = 0; kk < 4; kk++)
            got[kk] = __shfl_xor_sync(0xffffffffu, sent[kk], 1);
#pragma unroll
        for (int kk = 0; kk < 4; kk++) {
            const float2 r = unpk2(add2(mine[kk], got[kk]));
            *reinterpret_cast<float2*>(oa + (size_t)(k + kk) * N_) =
                make_float2(r.x, r.y);
        }
    }
}

// ---------------- kernel 2: in-CTA compaction + gather + dispatch ----------------
__global__ __launch_bounds__(256, 2)
void attn_kernel(const float* __restrict__ img,
                 const int* __restrict__ mask,
                 float* __restrict__ out_attn,
                 float* __restrict__ out_coef) {
    __shared__ __align__(16) float svf[DH_ * T_];
    __shared__ __align__(8) float scs[T_];
    __shared__ int stl[T_];
    __shared__ int sjm;

    const int b = blockIdx.y;
    const int tid = threadIdx.x;
    const int lane = tid & 31;
    const int warp = tid >> 5;
    const int half = lane & 1;
    const int pair = lane >> 1;
    const int n0 = blockIdx.x * 512 + warp * 64 + pair * 4;

    // in-CTA mask compaction (warp 0)
    if (tid < 32) {
        const int m = mask[b * T_ + tid];
        const unsigned bal = __ballot_sync(0xffffffffu, m == 0);
        const int Tc = __popc(bal);
        int Tcp = (Tc + 7) & ~7;
        if (Tcp < 8) Tcp = 8;
        if (m == 0) {
            const int pos = __popc(bal & ((1u << tid) - 1u));
            stl[pos] = tid;
        }
        const unsigned mb = ~bal;
        const int firstMasked = mb ? (__ffs(mb) - 1) : 0;
        if (tid >= Tc) stl[tid] = firstMasked;
        scs[tid] = (tid < Tc) ? 0.0f : -CUDART_INF_F;
        if (tid == 0) sjm = Tcp >> 3;
    }
    __syncthreads();

    // gather compact values rows (permutation within 128B lines -> coalesced)
    const float* gvb = g_values + (size_t)b * DH_ * T_;
#pragma unroll
    for (int i = 0; i < 16; i++) {
        const int f = tid + 256 * i;
        svf[f] = gvb[(f & ~31) + stl[f & 31]];
    }
    __syncthreads();

    const int jm = sjm;

    const float4* qb =
        reinterpret_cast<const float4*>(img + (size_t)b * DH_ * N_ + n0);
    float* ocb = out_coef + ((size_t)b * N_ + n0) * T_;
    float* oa = out_attn + (size_t)b * DH_ * N_ + n0 + 2 * half;
    const ulonglong2* sv = reinterpret_cast<const ulonglong2*>(svf);

    if (jm == 2)
        attn_core<2>(sv, scs, stl, qb, ocb, oa, half);
    else if (jm == 3)
        attn_core<3>(sv, scs, stl, qb, ocb, oa, half);
    else if (jm == 4)
        attn_core<4>(sv, scs, stl, qb, ocb, oa, half);
    else
        attn_core<1>(sv, scs, stl, qb, ocb, oa, half);
}

extern "C" void kernel_launch(void* const* d_in, const int* in_sizes, int n_in,
                              void* d_out, int out_size) {
    const float* wf   = (const float*)d_in[0];
    const float* img  = (const float*)d_in[1];
    const int*   msk  = (const int*)d_in[2];
    const float* Wm   = (const float*)d_in[3];
    const float* bias = (const float*)d_in[4];

    float* out_attn = (float*)d_out;
    float* out_coef = (float*)d_out + (size_t)B_ * DH_ * N_;

    dim3 vgrid(4, B_);
    values_kernel<<<vgrid, 256>>>(wf, Wm, bias);

    dim3 grid(N_ / 512, B_);
    attn_kernel<<<grid, 256>>>(img, msk, out_attn, out_coef);
}